// round 1
// baseline (speedup 1.0000x reference)
#include <cuda_runtime.h>
#include <math.h>

#define BATCH 8
#define NA    261888
#define KTOP  6000
#define PROP  1000
#define SHIFT 14
#define NBUCK (1 << 18)
#define CAP   8192
#define SORTN 8192

#define NMS_THREADS 768
#define BPT 8   /* boxes per thread: 768*8 = 6144 >= 6000 */

/* ---------------- device scratch (static: no allocation allowed) -------- */
__device__ unsigned int       g_hist[BATCH][NBUCK];     /* counts -> fill bases */
__device__ unsigned int       g_maxbucket[BATCH];
__device__ int                g_thresh[BATCH];
__device__ unsigned int       g_total[BATCH];
__device__ unsigned long long g_cand[BATCH][CAP];
__device__ float4             g_boxes[BATCH * KTOP];
__device__ float              g_areas[BATCH * KTOP];

/* order-preserving float -> uint key */
__device__ __forceinline__ unsigned int fkey(float s) {
    unsigned int u = __float_as_uint(s);
    return u ^ ((unsigned int)((int)u >> 31) | 0x80000000u);
}

/* ---------------- kernel 0: clear scratch ------------------------------ */
__global__ void clear_kernel() {
    size_t tid    = (size_t)blockIdx.x * blockDim.x + threadIdx.x;
    size_t stride = (size_t)gridDim.x * blockDim.x;
    uint4* h4 = (uint4*)&g_hist[0][0];
    size_t n4 = (size_t)BATCH * NBUCK / 4;
    uint4 z4 = make_uint4(0, 0, 0, 0);
    for (size_t i = tid; i < n4; i += stride) h4[i] = z4;
    unsigned long long* c = &g_cand[0][0];
    for (size_t i = tid; i < (size_t)BATCH * CAP; i += stride) c[i] = 0ull;
    if (tid < BATCH) g_maxbucket[tid] = 0u;
}

/* ---------------- kernel 1: per-batch bucket histogram ------------------ */
__global__ void hist_kernel(const float* __restrict__ probs) {
    int b = blockIdx.y;
    const float* p = probs + (size_t)b * NA * 2;
    unsigned int lmax = 0;
    for (int a = blockIdx.x * blockDim.x + threadIdx.x; a < NA;
         a += gridDim.x * blockDim.x) {
        unsigned int key = fkey(p[2 * a + 1]);
        unsigned int bk = key >> SHIFT;
        atomicAdd(&g_hist[b][bk], 1u);
        lmax = max(lmax, bk);
    }
    __shared__ unsigned int sm[256];
    sm[threadIdx.x] = lmax;
    __syncthreads();
    for (int o = 128; o > 0; o >>= 1) {
        if (threadIdx.x < o) sm[threadIdx.x] = max(sm[threadIdx.x], sm[threadIdx.x + o]);
        __syncthreads();
    }
    if (threadIdx.x == 0) atomicMax(&g_maxbucket[b], sm[0]);
}

/* ---------------- kernel 2: find threshold bucket, write fill bases ----- */
__global__ void findthresh_kernel() {
    int b = blockIdx.x, tid = threadIdx.x;
    __shared__ unsigned int scnt[256];
    __shared__ unsigned int s_running;
    if (tid == 0) s_running = 0;
    __syncthreads();
    int start = (int)g_maxbucket[b];
    for (int cs = start; cs >= 0; cs -= 256) {
        int bk = cs - tid;                       /* descending buckets */
        unsigned int c = (bk >= 0) ? g_hist[b][bk] : 0u;
        scnt[tid] = c;
        __syncthreads();
        for (int off = 1; off < 256; off <<= 1) {  /* inclusive scan over tid */
            unsigned int v = (tid >= off) ? scnt[tid - off] : 0u;
            __syncthreads();
            scnt[tid] += v;
            __syncthreads();
        }
        unsigned int incl = scnt[tid];
        unsigned int excl = incl - c;
        unsigned int run = s_running;
        if (bk >= 0 && run + excl < KTOP) {      /* bucket is included */
            g_hist[b][bk] = run + excl;          /* counting-sort base offset */
            if (run + incl >= KTOP) {            /* crossing: threshold bucket */
                g_thresh[b] = bk;
                g_total[b]  = run + incl;
            }
        }
        __syncthreads();
        if (tid == 0) s_running = run + scnt[255];
        __syncthreads();
        if (s_running >= KTOP) break;
    }
}

/* ---------------- kernel 3: compact candidates (grouped by bucket) ------ */
__global__ void compact_kernel(const float* __restrict__ probs) {
    int b = blockIdx.y;
    int tb = g_thresh[b];
    const float* p = probs + (size_t)b * NA * 2;
    for (int a = blockIdx.x * blockDim.x + threadIdx.x; a < NA;
         a += gridDim.x * blockDim.x) {
        unsigned int key = fkey(p[2 * a + 1]);
        unsigned int bk = key >> SHIFT;
        if ((int)bk >= tb) {
            unsigned int pos = atomicAdd(&g_hist[b][bk], 1u);
            if (pos < CAP)
                g_cand[b][pos] =
                    ((unsigned long long)key << 32) | (unsigned int)(~a);
        }
    }
}

/* ---------------- kernel 4: bitonic sort + gather + box decode ---------- */
__global__ void __launch_bounds__(1024, 1)
sort_gather_kernel(const float* __restrict__ bbox,
                   const float* __restrict__ anchors) {
    extern __shared__ unsigned long long s[];
    int b = blockIdx.x, tid = threadIdx.x;
    for (int i = tid; i < SORTN; i += blockDim.x) s[i] = g_cand[b][i];
    __syncthreads();
    for (int k = 2; k <= SORTN; k <<= 1) {
        for (int j = k >> 1; j > 0; j >>= 1) {
            for (int i = tid; i < SORTN; i += blockDim.x) {
                int ixj = i ^ j;
                if (ixj > i) {
                    unsigned long long x = s[i], y = s[ixj];
                    bool up = ((i & k) == 0);    /* descending overall */
                    if (up ? (x < y) : (x > y)) { s[i] = y; s[ixj] = x; }
                }
            }
            __syncthreads();
        }
    }
    /* gather top-K rows, apply deltas, clip, store boxes+areas */
    const float4* anc = (const float4*)(anchors + (size_t)b * NA * 4);
    const float4* dl  = (const float4*)(bbox    + (size_t)b * NA * 4);
    for (int i = tid; i < KTOP; i += blockDim.x) {
        unsigned int idx = ~(unsigned int)(s[i]);     /* low 32 bits inverted */
        float4 a4 = anc[idx];
        float4 r4 = dl[idx];
        /* deltas = rpn_bbox * [0.1,0.1,0.2,0.2]  (separate muls, no FMA) */
        float d0 = __fmul_rn(r4.x, 0.1f);
        float d1 = __fmul_rn(r4.y, 0.1f);
        float d2 = __fmul_rn(r4.z, 0.2f);
        float d3 = __fmul_rn(r4.w, 0.2f);
        float h  = __fsub_rn(a4.z, a4.x);
        float w  = __fsub_rn(a4.w, a4.y);
        float cy = __fadd_rn(__fadd_rn(a4.x, __fmul_rn(0.5f, h)), __fmul_rn(d0, h));
        float cx = __fadd_rn(__fadd_rn(a4.y, __fmul_rn(0.5f, w)), __fmul_rn(d1, w));
        float h2 = __fmul_rn(h, expf(d2));
        float w2 = __fmul_rn(w, expf(d3));
        float y1 = __fsub_rn(cy, __fmul_rn(0.5f, h2));
        float x1 = __fsub_rn(cx, __fmul_rn(0.5f, w2));
        float y2 = __fadd_rn(y1, h2);
        float x2 = __fadd_rn(x1, w2);
        y1 = fminf(fmaxf(y1, 0.0f), 1.0f);
        x1 = fminf(fmaxf(x1, 0.0f), 1.0f);
        y2 = fminf(fmaxf(y2, 0.0f), 1.0f);
        x2 = fminf(fmaxf(x2, 0.0f), 1.0f);
        g_boxes[b * KTOP + i] = make_float4(y1, x1, y2, x2);
        g_areas[b * KTOP + i] = __fmul_rn(__fsub_rn(y2, y1), __fsub_rn(x2, x1));
    }
}

/* ---------------- kernel 5: greedy sequential NMS ----------------------- */
#define NMS_SMEM (96000 + 24000 + 6144)

__global__ void __launch_bounds__(NMS_THREADS, 1)
nms_kernel(float* __restrict__ out) {
    int b = blockIdx.x, tid = threadIdx.x;
    extern __shared__ unsigned char smraw[];
    float4*        sbox   = (float4*)smraw;                 /* 6000 * 16B */
    float*         sarea  = (float*)(smraw + 96000);        /* 6000 * 4B  */
    unsigned char* svalid = smraw + 120000;                 /* 6144 bytes */
    __shared__ int s_pick;

    const float4* boxes = g_boxes + b * KTOP;
    const float*  areas = g_areas + b * KTOP;

    for (int i = tid; i < KTOP; i += NMS_THREADS) {
        sbox[i]   = boxes[i];
        sarea[i]  = areas[i];
        svalid[i] = 1;
    }
    /* register-resident chunk of 8 contiguous boxes per thread */
    int base = tid * BPT;
    float4 mb[BPT];
    float  ma[BPT];
    unsigned int alive = 0;
#pragma unroll
    for (int r = 0; r < BPT; r++) {
        int g = base + r;
        if (g < KTOP) {
            mb[r] = boxes[g];
            ma[r] = areas[g];
            alive |= 1u << r;
        }
    }
    __syncthreads();

    int cur = 0;  /* only meaningful on tid 0; first-valid index is monotone */
    for (int step = 0; step < PROP; ++step) {
        if (tid == 0) {
            while (cur < KTOP && !svalid[cur]) cur++;
            s_pick = (cur < KTOP) ? cur : -1;
        }
        __syncthreads();
        int pick = s_pick;
        float4 pb = make_float4(0.f, 0.f, 0.f, 0.f);
        float  pA = 0.f;
        if (pick >= 0) { pb = sbox[pick]; pA = sarea[pick]; }
        if (tid == 0) {
            ((float4*)out)[b * PROP + step] = pb;  /* zeros when no pick */
        }
        if (pick >= 0 && alive) {
#pragma unroll
            for (int r = 0; r < BPT; r++) {
                if (alive & (1u << r)) {
                    float yy1 = fmaxf(pb.x, mb[r].x);
                    float xx1 = fmaxf(pb.y, mb[r].y);
                    float yy2 = fminf(pb.z, mb[r].z);
                    float xx2 = fminf(pb.w, mb[r].w);
                    float inter = __fmul_rn(fmaxf(__fsub_rn(yy2, yy1), 0.0f),
                                            fmaxf(__fsub_rn(xx2, xx1), 0.0f));
                    float uni = __fsub_rn(__fadd_rn(pA, ma[r]), inter);
                    float iou = (uni > 0.0f) ? __fdiv_rn(inter, uni) : 0.0f;
                    if (!(iou <= 0.7f)) {   /* suppress (self included: iou=1) */
                        alive &= ~(1u << r);
                        svalid[base + r] = 0;
                    }
                }
            }
        }
        __syncthreads();
    }
}

/* ---------------- launch ------------------------------------------------ */
extern "C" void kernel_launch(void* const* d_in, const int* in_sizes, int n_in,
                              void* d_out, int out_size) {
    const float* probs   = (const float*)d_in[0];  /* (B, A, 2) */
    const float* bbox    = (const float*)d_in[1];  /* (B, A, 4) */
    const float* anchors = (const float*)d_in[2];  /* (B, A, 4) */
    float* out = (float*)d_out;                    /* (B, 1000, 4) */

    cudaFuncSetAttribute(sort_gather_kernel,
                         cudaFuncAttributeMaxDynamicSharedMemorySize, SORTN * 8);
    cudaFuncSetAttribute(nms_kernel,
                         cudaFuncAttributeMaxDynamicSharedMemorySize, NMS_SMEM);

    clear_kernel<<<1024, 256>>>();
    dim3 hg(256, BATCH);
    hist_kernel<<<hg, 256>>>(probs);
    findthresh_kernel<<<BATCH, 256>>>();
    compact_kernel<<<hg, 256>>>(probs);
    sort_gather_kernel<<<BATCH, 1024, SORTN * 8>>>(bbox, anchors);
    nms_kernel<<<BATCH, NMS_THREADS, NMS_SMEM>>>(out);
}

// round 2
// speedup vs baseline: 2.0268x; 2.0268x over previous
#include <cuda_runtime.h>
#include <math.h>

#define BATCH 8
#define NA    261888
#define KTOP  6000
#define PROP  1000
#define SHIFT 14
#define NBUCK (1 << 18)
#define CAP   8192
#define SORTN 8192

#define NMS_THREADS 768
#define BPT 8   /* boxes per thread: 768*8 = 6144 >= 6000 */

/* ---------------- device scratch (static: no allocation allowed) -------- */
__device__ unsigned int       g_hist[BATCH][NBUCK];     /* counts -> fill bases */
__device__ unsigned int       g_maxbucket[BATCH];
__device__ int                g_thresh[BATCH];
__device__ unsigned int       g_total[BATCH];
__device__ unsigned long long g_cand[BATCH][CAP];
__device__ float4             g_boxes[BATCH * KTOP];
__device__ float              g_areas[BATCH * KTOP];

/* order-preserving float -> uint key */
__device__ __forceinline__ unsigned int fkey(float s) {
    unsigned int u = __float_as_uint(s);
    return u ^ ((unsigned int)((int)u >> 31) | 0x80000000u);
}

/* ---------------- kernel 0: clear scratch ------------------------------ */
__global__ void clear_kernel() {
    size_t tid    = (size_t)blockIdx.x * blockDim.x + threadIdx.x;
    size_t stride = (size_t)gridDim.x * blockDim.x;
    uint4* h4 = (uint4*)&g_hist[0][0];
    size_t n4 = (size_t)BATCH * NBUCK / 4;
    uint4 z4 = make_uint4(0, 0, 0, 0);
    for (size_t i = tid; i < n4; i += stride) h4[i] = z4;
    unsigned long long* c = &g_cand[0][0];
    for (size_t i = tid; i < (size_t)BATCH * CAP; i += stride) c[i] = 0ull;
    if (tid < BATCH) g_maxbucket[tid] = 0u;
}

/* ---------------- kernel 1: per-batch bucket histogram ------------------ */
__global__ void hist_kernel(const float* __restrict__ probs) {
    int b = blockIdx.y;
    const float* p = probs + (size_t)b * NA * 2;
    unsigned int lmax = 0;
    for (int a = blockIdx.x * blockDim.x + threadIdx.x; a < NA;
         a += gridDim.x * blockDim.x) {
        unsigned int key = fkey(p[2 * a + 1]);
        unsigned int bk = key >> SHIFT;
        atomicAdd(&g_hist[b][bk], 1u);
        lmax = max(lmax, bk);
    }
    __shared__ unsigned int sm[256];
    sm[threadIdx.x] = lmax;
    __syncthreads();
    for (int o = 128; o > 0; o >>= 1) {
        if (threadIdx.x < o) sm[threadIdx.x] = max(sm[threadIdx.x], sm[threadIdx.x + o]);
        __syncthreads();
    }
    if (threadIdx.x == 0) atomicMax(&g_maxbucket[b], sm[0]);
}

/* ---------------- kernel 2: find threshold bucket, write fill bases ----- */
__global__ void findthresh_kernel() {
    int b = blockIdx.x, tid = threadIdx.x;
    __shared__ unsigned int scnt[256];
    __shared__ unsigned int s_running;
    if (tid == 0) s_running = 0;
    __syncthreads();
    int start = (int)g_maxbucket[b];
    for (int cs = start; cs >= 0; cs -= 256) {
        int bk = cs - tid;                       /* descending buckets */
        unsigned int c = (bk >= 0) ? g_hist[b][bk] : 0u;
        scnt[tid] = c;
        __syncthreads();
        for (int off = 1; off < 256; off <<= 1) {  /* inclusive scan over tid */
            unsigned int v = (tid >= off) ? scnt[tid - off] : 0u;
            __syncthreads();
            scnt[tid] += v;
            __syncthreads();
        }
        unsigned int incl = scnt[tid];
        unsigned int excl = incl - c;
        unsigned int run = s_running;
        if (bk >= 0 && run + excl < KTOP) {      /* bucket is included */
            g_hist[b][bk] = run + excl;          /* counting-sort base offset */
            if (run + incl >= KTOP) {            /* crossing: threshold bucket */
                g_thresh[b] = bk;
                g_total[b]  = run + incl;
            }
        }
        __syncthreads();
        if (tid == 0) s_running = run + scnt[255];
        __syncthreads();
        if (s_running >= KTOP) break;
    }
}

/* ---------------- kernel 3: compact candidates (grouped by bucket) ------ */
__global__ void compact_kernel(const float* __restrict__ probs) {
    int b = blockIdx.y;
    int tb = g_thresh[b];
    const float* p = probs + (size_t)b * NA * 2;
    for (int a = blockIdx.x * blockDim.x + threadIdx.x; a < NA;
         a += gridDim.x * blockDim.x) {
        unsigned int key = fkey(p[2 * a + 1]);
        unsigned int bk = key >> SHIFT;
        if ((int)bk >= tb) {
            unsigned int pos = atomicAdd(&g_hist[b][bk], 1u);
            if (pos < CAP)
                g_cand[b][pos] =
                    ((unsigned long long)key << 32) | (unsigned int)(~a);
        }
    }
}

/* ---------------- kernel 4: bitonic sort + gather + box decode ---------- */
__global__ void __launch_bounds__(1024, 1)
sort_gather_kernel(const float* __restrict__ bbox,
                   const float* __restrict__ anchors) {
    extern __shared__ unsigned long long s[];
    int b = blockIdx.x, tid = threadIdx.x;
    for (int i = tid; i < SORTN; i += blockDim.x) s[i] = g_cand[b][i];
    __syncthreads();
    for (int k = 2; k <= SORTN; k <<= 1) {
        for (int j = k >> 1; j > 0; j >>= 1) {
            for (int i = tid; i < SORTN; i += blockDim.x) {
                int ixj = i ^ j;
                if (ixj > i) {
                    unsigned long long x = s[i], y = s[ixj];
                    bool up = ((i & k) == 0);    /* descending overall */
                    if (up ? (x < y) : (x > y)) { s[i] = y; s[ixj] = x; }
                }
            }
            __syncthreads();
        }
    }
    /* gather top-K rows, apply deltas, clip, store boxes+areas */
    const float4* anc = (const float4*)(anchors + (size_t)b * NA * 4);
    const float4* dl  = (const float4*)(bbox    + (size_t)b * NA * 4);
    for (int i = tid; i < KTOP; i += blockDim.x) {
        unsigned int idx = ~(unsigned int)(s[i]);     /* low 32 bits inverted */
        float4 a4 = anc[idx];
        float4 r4 = dl[idx];
        /* deltas = rpn_bbox * [0.1,0.1,0.2,0.2]  (separate muls, no FMA) */
        float d0 = __fmul_rn(r4.x, 0.1f);
        float d1 = __fmul_rn(r4.y, 0.1f);
        float d2 = __fmul_rn(r4.z, 0.2f);
        float d3 = __fmul_rn(r4.w, 0.2f);
        float h  = __fsub_rn(a4.z, a4.x);
        float w  = __fsub_rn(a4.w, a4.y);
        float cy = __fadd_rn(__fadd_rn(a4.x, __fmul_rn(0.5f, h)), __fmul_rn(d0, h));
        float cx = __fadd_rn(__fadd_rn(a4.y, __fmul_rn(0.5f, w)), __fmul_rn(d1, w));
        float h2 = __fmul_rn(h, expf(d2));
        float w2 = __fmul_rn(w, expf(d3));
        float y1 = __fsub_rn(cy, __fmul_rn(0.5f, h2));
        float x1 = __fsub_rn(cx, __fmul_rn(0.5f, w2));
        float y2 = __fadd_rn(y1, h2);
        float x2 = __fadd_rn(x1, w2);
        y1 = fminf(fmaxf(y1, 0.0f), 1.0f);
        x1 = fminf(fmaxf(x1, 0.0f), 1.0f);
        y2 = fminf(fmaxf(y2, 0.0f), 1.0f);
        x2 = fminf(fmaxf(x2, 0.0f), 1.0f);
        g_boxes[b * KTOP + i] = make_float4(y1, x1, y2, x2);
        g_areas[b * KTOP + i] = __fmul_rn(__fsub_rn(y2, y1), __fsub_rn(x2, x1));
    }
}

/* ---------------- kernel 5: greedy sequential NMS ----------------------- */
#define NMS_SMEM (96000 + 24000 + 6144)

__global__ void __launch_bounds__(NMS_THREADS, 1)
nms_kernel(float* __restrict__ out) {
    int b = blockIdx.x, tid = threadIdx.x;
    extern __shared__ unsigned char smraw[];
    float4*        sbox   = (float4*)smraw;                 /* 6000 * 16B */
    float*         sarea  = (float*)(smraw + 96000);        /* 6000 * 4B  */
    unsigned char* svalid = smraw + 120000;                 /* 6144 bytes */
    __shared__ int s_pick;

    const float4* boxes = g_boxes + b * KTOP;
    const float*  areas = g_areas + b * KTOP;

    for (int i = tid; i < KTOP; i += NMS_THREADS) {
        sbox[i]   = boxes[i];
        sarea[i]  = areas[i];
        svalid[i] = 1;
    }
    /* register-resident chunk of 8 contiguous boxes per thread */
    int base = tid * BPT;
    float4 mb[BPT];
    float  ma[BPT];
    unsigned int alive = 0;
#pragma unroll
    for (int r = 0; r < BPT; r++) {
        int g = base + r;
        if (g < KTOP) {
            mb[r] = boxes[g];
            ma[r] = areas[g];
            alive |= 1u << r;
        }
    }
    __syncthreads();

    int cur = 0;  /* only meaningful on tid 0; first-valid index is monotone */
    for (int step = 0; step < PROP; ++step) {
        if (tid == 0) {
            while (cur < KTOP && !svalid[cur]) cur++;
            s_pick = (cur < KTOP) ? cur : -1;
        }
        __syncthreads();
        int pick = s_pick;
        float4 pb = make_float4(0.f, 0.f, 0.f, 0.f);
        float  pA = 0.f;
        if (pick >= 0) { pb = sbox[pick]; pA = sarea[pick]; }
        if (tid == 0) {
            ((float4*)out)[b * PROP + step] = pb;  /* zeros when no pick */
        }
        /* Everything strictly below `pick` is already invalid (pick is the
           FIRST valid index), so whole chunks below it can be skipped.     */
        if (pick >= 0 && alive && (base + BPT) > pick) {
#pragma unroll
            for (int r = 0; r < BPT; r++) {
                if (alive & (1u << r)) {
                    float yy1 = fmaxf(pb.x, mb[r].x);
                    float xx1 = fmaxf(pb.y, mb[r].y);
                    float yy2 = fminf(pb.z, mb[r].z);
                    float xx2 = fminf(pb.w, mb[r].w);
                    float inter = __fmul_rn(fmaxf(__fsub_rn(yy2, yy1), 0.0f),
                                            fmaxf(__fsub_rn(xx2, xx1), 0.0f));
                    /* Exact shortcut: inter==0 -> iou==0 -> keep.
                       uni<=0  -> reference's where() gives iou=0 -> keep.  */
                    if (inter > 0.0f) {
                        float uni = __fsub_rn(__fadd_rn(pA, ma[r]), inter);
                        if (uni > 0.0f) {
                            float iou = __fdiv_rn(inter, uni);
                            if (!(iou <= 0.7f)) {
                                alive &= ~(1u << r);
                                svalid[base + r] = 0;
                            }
                        }
                    }
                }
            }
        }
        __syncthreads();
    }
}

/* ---------------- launch ------------------------------------------------ */
extern "C" void kernel_launch(void* const* d_in, const int* in_sizes, int n_in,
                              void* d_out, int out_size) {
    const float* probs   = (const float*)d_in[0];  /* (B, A, 2) */
    const float* bbox    = (const float*)d_in[1];  /* (B, A, 4) */
    const float* anchors = (const float*)d_in[2];  /* (B, A, 4) */
    float* out = (float*)d_out;                    /* (B, 1000, 4) */

    cudaFuncSetAttribute(sort_gather_kernel,
                         cudaFuncAttributeMaxDynamicSharedMemorySize, SORTN * 8);
    cudaFuncSetAttribute(nms_kernel,
                         cudaFuncAttributeMaxDynamicSharedMemorySize, NMS_SMEM);

    clear_kernel<<<1024, 256>>>();
    dim3 hg(256, BATCH);
    hist_kernel<<<hg, 256>>>(probs);
    findthresh_kernel<<<BATCH, 256>>>();
    compact_kernel<<<hg, 256>>>(probs);
    sort_gather_kernel<<<BATCH, 1024, SORTN * 8>>>(bbox, anchors);
    nms_kernel<<<BATCH, NMS_THREADS, NMS_SMEM>>>(out);
}

// round 3
// speedup vs baseline: 2.2651x; 1.1176x over previous
#include <cuda_runtime.h>
#include <math.h>

#define BATCH 8
#define NA    261888
#define KTOP  6000
#define PROP  1000
#define SHIFT 14
#define NBUCK (1 << 18)
#define CAP   8192
#define SORTN 8192

#define MASKW32 192          /* u32 words per mask row (= 96 u64, 6144 bits) */
#define MASKW64 96

/* ---------------- device scratch (static: no allocation allowed) -------- */
__device__ unsigned int       g_hist[BATCH][NBUCK];
__device__ unsigned int       g_maxbucket[BATCH];
__device__ int                g_thresh[BATCH];
__device__ unsigned int       g_total[BATCH];
__device__ unsigned long long g_cand[BATCH][CAP];
__device__ float4             g_boxes[BATCH * KTOP];
__device__ float              g_areas[BATCH * KTOP];
__device__ unsigned int       g_mask[BATCH][KTOP][MASKW32];   /* ~37 MB */

/* order-preserving float -> uint key */
__device__ __forceinline__ unsigned int fkey(float s) {
    unsigned int u = __float_as_uint(s);
    return u ^ ((unsigned int)((int)u >> 31) | 0x80000000u);
}

/* ---------------- kernel 0: clear scratch ------------------------------ */
__global__ void clear_kernel() {
    size_t tid    = (size_t)blockIdx.x * blockDim.x + threadIdx.x;
    size_t stride = (size_t)gridDim.x * blockDim.x;
    uint4* h4 = (uint4*)&g_hist[0][0];
    size_t n4 = (size_t)BATCH * NBUCK / 4;
    uint4 z4 = make_uint4(0, 0, 0, 0);
    for (size_t i = tid; i < n4; i += stride) h4[i] = z4;
    unsigned long long* c = &g_cand[0][0];
    for (size_t i = tid; i < (size_t)BATCH * CAP; i += stride) c[i] = 0ull;
    if (tid < BATCH) g_maxbucket[tid] = 0u;
}

/* ---------------- kernel 1: per-batch bucket histogram ------------------ */
__global__ void hist_kernel(const float* __restrict__ probs) {
    int b = blockIdx.y;
    const float* p = probs + (size_t)b * NA * 2;
    unsigned int lmax = 0;
    for (int a = blockIdx.x * blockDim.x + threadIdx.x; a < NA;
         a += gridDim.x * blockDim.x) {
        unsigned int key = fkey(p[2 * a + 1]);
        unsigned int bk = key >> SHIFT;
        atomicAdd(&g_hist[b][bk], 1u);
        lmax = max(lmax, bk);
    }
    __shared__ unsigned int sm[256];
    sm[threadIdx.x] = lmax;
    __syncthreads();
    for (int o = 128; o > 0; o >>= 1) {
        if (threadIdx.x < o) sm[threadIdx.x] = max(sm[threadIdx.x], sm[threadIdx.x + o]);
        __syncthreads();
    }
    if (threadIdx.x == 0) atomicMax(&g_maxbucket[b], sm[0]);
}

/* ---------------- kernel 2: find threshold bucket, write fill bases ----- */
__global__ void findthresh_kernel() {
    int b = blockIdx.x, tid = threadIdx.x;
    __shared__ unsigned int scnt[256];
    __shared__ unsigned int s_running;
    if (tid == 0) s_running = 0;
    __syncthreads();
    int start = (int)g_maxbucket[b];
    for (int cs = start; cs >= 0; cs -= 256) {
        int bk = cs - tid;
        unsigned int c = (bk >= 0) ? g_hist[b][bk] : 0u;
        scnt[tid] = c;
        __syncthreads();
        for (int off = 1; off < 256; off <<= 1) {
            unsigned int v = (tid >= off) ? scnt[tid - off] : 0u;
            __syncthreads();
            scnt[tid] += v;
            __syncthreads();
        }
        unsigned int incl = scnt[tid];
        unsigned int excl = incl - c;
        unsigned int run = s_running;
        if (bk >= 0 && run + excl < KTOP) {
            g_hist[b][bk] = run + excl;
            if (run + incl >= KTOP) {
                g_thresh[b] = bk;
                g_total[b]  = run + incl;
            }
        }
        __syncthreads();
        if (tid == 0) s_running = run + scnt[255];
        __syncthreads();
        if (s_running >= KTOP) break;
    }
}

/* ---------------- kernel 3: compact candidates (grouped by bucket) ------ */
__global__ void compact_kernel(const float* __restrict__ probs) {
    int b = blockIdx.y;
    int tb = g_thresh[b];
    const float* p = probs + (size_t)b * NA * 2;
    for (int a = blockIdx.x * blockDim.x + threadIdx.x; a < NA;
         a += gridDim.x * blockDim.x) {
        unsigned int key = fkey(p[2 * a + 1]);
        unsigned int bk = key >> SHIFT;
        if ((int)bk >= tb) {
            unsigned int pos = atomicAdd(&g_hist[b][bk], 1u);
            if (pos < CAP)
                g_cand[b][pos] =
                    ((unsigned long long)key << 32) | (unsigned int)(~a);
        }
    }
}

/* ---------------- kernel 4: bitonic sort + gather + box decode ---------- */
__global__ void __launch_bounds__(1024, 1)
sort_gather_kernel(const float* __restrict__ bbox,
                   const float* __restrict__ anchors) {
    extern __shared__ unsigned long long s[];
    int b = blockIdx.x, tid = threadIdx.x;
    for (int i = tid; i < SORTN; i += blockDim.x) s[i] = g_cand[b][i];
    __syncthreads();
    for (int k = 2; k <= SORTN; k <<= 1) {
        for (int j = k >> 1; j > 0; j >>= 1) {
            for (int i = tid; i < SORTN; i += blockDim.x) {
                int ixj = i ^ j;
                if (ixj > i) {
                    unsigned long long x = s[i], y = s[ixj];
                    bool up = ((i & k) == 0);
                    if (up ? (x < y) : (x > y)) { s[i] = y; s[ixj] = x; }
                }
            }
            __syncthreads();
        }
    }
    const float4* anc = (const float4*)(anchors + (size_t)b * NA * 4);
    const float4* dl  = (const float4*)(bbox    + (size_t)b * NA * 4);
    for (int i = tid; i < KTOP; i += blockDim.x) {
        unsigned int idx = ~(unsigned int)(s[i]);
        float4 a4 = anc[idx];
        float4 r4 = dl[idx];
        float d0 = __fmul_rn(r4.x, 0.1f);
        float d1 = __fmul_rn(r4.y, 0.1f);
        float d2 = __fmul_rn(r4.z, 0.2f);
        float d3 = __fmul_rn(r4.w, 0.2f);
        float h  = __fsub_rn(a4.z, a4.x);
        float w  = __fsub_rn(a4.w, a4.y);
        float cy = __fadd_rn(__fadd_rn(a4.x, __fmul_rn(0.5f, h)), __fmul_rn(d0, h));
        float cx = __fadd_rn(__fadd_rn(a4.y, __fmul_rn(0.5f, w)), __fmul_rn(d1, w));
        float h2 = __fmul_rn(h, expf(d2));
        float w2 = __fmul_rn(w, expf(d3));
        float y1 = __fsub_rn(cy, __fmul_rn(0.5f, h2));
        float x1 = __fsub_rn(cx, __fmul_rn(0.5f, w2));
        float y2 = __fadd_rn(y1, h2);
        float x2 = __fadd_rn(x1, w2);
        y1 = fminf(fmaxf(y1, 0.0f), 1.0f);
        x1 = fminf(fmaxf(x1, 0.0f), 1.0f);
        y2 = fminf(fmaxf(y2, 0.0f), 1.0f);
        x2 = fminf(fmaxf(x2, 0.0f), 1.0f);
        g_boxes[b * KTOP + i] = make_float4(y1, x1, y2, x2);
        g_areas[b * KTOP + i] = __fmul_rn(__fsub_rn(y2, y1), __fsub_rn(x2, x1));
    }
}

/* ---------------- kernel 5: parallel suppression-mask build ------------- */
#define MB_ROWS 128
#define MB_CHUNK 128

__global__ void __launch_bounds__(MB_ROWS)
mask_build_kernel() {
    int b   = blockIdx.y;
    int tid = threadIdx.x;
    int i   = blockIdx.x * MB_ROWS + tid;          /* my row (pick index) */

    __shared__ float4 cb[MB_CHUNK];
    __shared__ float  ca[MB_CHUNK];

    float4 rb = make_float4(0.f, 0.f, 0.f, 0.f);
    float  ra = 0.f;
    if (i < KTOP) { rb = g_boxes[b * KTOP + i]; ra = g_areas[b * KTOP + i]; }

    for (int chunk = 0; chunk < KTOP; chunk += MB_CHUNK) {
        int j = chunk + tid;
        if (j < KTOP) { cb[tid] = g_boxes[b * KTOP + j]; ca[tid] = g_areas[b * KTOP + j]; }
        __syncthreads();
        if (i < KTOP) {
#pragma unroll
            for (int w = 0; w < MB_CHUNK / 32; ++w) {
                int base = chunk + w * 32;
                /* bits j < i are don't-cares; skip fully-below words */
                if (base + 31 >= i && base < KTOP) {
                    unsigned int word = 0;
                    for (int bit = 0; bit < 32; ++bit) {
                        int j2 = base + bit;
                        if (j2 < KTOP) {
                            float4 cbx = cb[w * 32 + bit];
                            float  cax = ca[w * 32 + bit];
                            float yy1 = fmaxf(rb.x, cbx.x);
                            float xx1 = fmaxf(rb.y, cbx.y);
                            float yy2 = fminf(rb.z, cbx.z);
                            float xx2 = fminf(rb.w, cbx.w);
                            float inter = __fmul_rn(fmaxf(__fsub_rn(yy2, yy1), 0.0f),
                                                    fmaxf(__fsub_rn(xx2, xx1), 0.0f));
                            if (inter > 0.0f) {
                                float uni = __fsub_rn(__fadd_rn(ra, cax), inter);
                                if (uni > 0.0f) {
                                    float iou = __fdiv_rn(inter, uni);
                                    if (!(iou <= 0.7f)) word |= (1u << bit);
                                }
                            }
                        }
                    }
                    g_mask[b][i][base / 32] = word;
                }
            }
        }
        __syncthreads();
    }
}

/* ---------------- kernel 6: warp-serial greedy pass --------------------- */
__global__ void __launch_bounds__(32, 1)
nms_serial_kernel(float* __restrict__ out) {
    int b    = blockIdx.x;
    int lane = threadIdx.x;
    __shared__ int s_picks[PROP];

    /* valid bitmap: u64 word wu = g*32 + lane covers bits [wu*64, wu*64+63].
       6000 bits: words 0..92 full, word 93 low 48 bits, 94..95 zero.      */
    unsigned long long V[3];
#pragma unroll
    for (int g = 0; g < 3; ++g) {
        int wu = g * 32 + lane;
        V[g] = (wu < 93) ? ~0ull
             : (wu == 93) ? ((1ull << 48) - 1ull) : 0ull;
    }

    const unsigned long long* mask64 =
        (const unsigned long long*)&g_mask[b][0][0];

    for (int step = 0; step < PROP; ++step) {
        /* first-set-bit scan: ballot per group, shfl the winning word */
        int pick = -1;
#pragma unroll
        for (int g = 0; g < 3; ++g) {
            if (pick < 0) {
                unsigned int ball = __ballot_sync(0xFFFFFFFFu, V[g] != 0ull);
                if (ball) {
                    int sel = __ffs(ball) - 1;
                    unsigned long long w = __shfl_sync(0xFFFFFFFFu, V[g], sel);
                    pick = g * 2048 + sel * 64 + (__ffsll((long long)w) - 1);
                }
            }
        }
        if (lane == 0) s_picks[step] = pick;
        if (pick < 0) continue;     /* exhausted: cheap empty scans remain */

        const unsigned long long* row = mask64 + (size_t)pick * MASKW64;
        unsigned long long m0 = row[lane];
        unsigned long long m1 = row[lane + 32];
        unsigned long long m2 = row[lane + 64];
        V[0] &= ~m0;
        V[1] &= ~m1;
        V[2] &= ~m2;
    }

    __syncwarp();
    /* parallel output gather */
    const float4* boxes = g_boxes + b * KTOP;
    float4* o = (float4*)out + b * PROP;
    for (int s = lane; s < PROP; s += 32) {
        int p = s_picks[s];
        o[s] = (p >= 0) ? boxes[p] : make_float4(0.f, 0.f, 0.f, 0.f);
    }
}

/* ---------------- launch ------------------------------------------------ */
extern "C" void kernel_launch(void* const* d_in, const int* in_sizes, int n_in,
                              void* d_out, int out_size) {
    const float* probs   = (const float*)d_in[0];  /* (B, A, 2) */
    const float* bbox    = (const float*)d_in[1];  /* (B, A, 4) */
    const float* anchors = (const float*)d_in[2];  /* (B, A, 4) */
    float* out = (float*)d_out;                    /* (B, 1000, 4) */

    cudaFuncSetAttribute(sort_gather_kernel,
                         cudaFuncAttributeMaxDynamicSharedMemorySize, SORTN * 8);

    clear_kernel<<<1024, 256>>>();
    dim3 hg(256, BATCH);
    hist_kernel<<<hg, 256>>>(probs);
    findthresh_kernel<<<BATCH, 256>>>();
    compact_kernel<<<hg, 256>>>(probs);
    sort_gather_kernel<<<BATCH, 1024, SORTN * 8>>>(bbox, anchors);
    dim3 mg((KTOP + MB_ROWS - 1) / MB_ROWS, BATCH);
    mask_build_kernel<<<mg, MB_ROWS>>>();
    nms_serial_kernel<<<BATCH, 32>>>(out);
}

// round 4
// speedup vs baseline: 3.4394x; 1.5184x over previous
#include <cuda_runtime.h>
#include <math.h>

#define BATCH 8
#define NA    261888
#define KTOP  6000
#define PROP  1000
#define SHIFT 14
#define NBUCK (1 << 18)
#define CAP   8192
#define SORTN 8192

#define MASKW32 192          /* u32 words per mask row (= 96 u64, 6144 bits) */
#define MASKW64 96

/* ---------------- device scratch (static: no allocation allowed) -------- */
__device__ unsigned int       g_hist[BATCH][NBUCK];
__device__ unsigned int       g_maxbucket[BATCH];
__device__ int                g_thresh[BATCH];
__device__ unsigned int       g_total[BATCH];
__device__ unsigned long long g_cand[BATCH][CAP];
__device__ float4             g_boxes[BATCH * KTOP];
__device__ float              g_areas[BATCH * KTOP];
__device__ unsigned int       g_mask[BATCH][KTOP][MASKW32];   /* ~37 MB */

/* order-preserving float -> uint key */
__device__ __forceinline__ unsigned int fkey(float s) {
    unsigned int u = __float_as_uint(s);
    return u ^ ((unsigned int)((int)u >> 31) | 0x80000000u);
}

/* ---------------- kernel 0: clear scratch ------------------------------ */
__global__ void clear_kernel() {
    size_t tid    = (size_t)blockIdx.x * blockDim.x + threadIdx.x;
    size_t stride = (size_t)gridDim.x * blockDim.x;
    uint4* h4 = (uint4*)&g_hist[0][0];
    size_t n4 = (size_t)BATCH * NBUCK / 4;
    uint4 z4 = make_uint4(0, 0, 0, 0);
    for (size_t i = tid; i < n4; i += stride) h4[i] = z4;
    unsigned long long* c = &g_cand[0][0];
    for (size_t i = tid; i < (size_t)BATCH * CAP; i += stride) c[i] = 0ull;
    if (tid < BATCH) g_maxbucket[tid] = 0u;
}

/* ---------------- kernel 1: per-batch bucket histogram ------------------ */
__global__ void hist_kernel(const float* __restrict__ probs) {
    int b = blockIdx.y;
    const float* p = probs + (size_t)b * NA * 2;
    unsigned int lmax = 0;
    for (int a = blockIdx.x * blockDim.x + threadIdx.x; a < NA;
         a += gridDim.x * blockDim.x) {
        unsigned int key = fkey(p[2 * a + 1]);
        unsigned int bk = key >> SHIFT;
        atomicAdd(&g_hist[b][bk], 1u);
        lmax = max(lmax, bk);
    }
    __shared__ unsigned int sm[256];
    sm[threadIdx.x] = lmax;
    __syncthreads();
    for (int o = 128; o > 0; o >>= 1) {
        if (threadIdx.x < o) sm[threadIdx.x] = max(sm[threadIdx.x], sm[threadIdx.x + o]);
        __syncthreads();
    }
    if (threadIdx.x == 0) atomicMax(&g_maxbucket[b], sm[0]);
}

/* ---------------- kernel 2: find threshold bucket, write fill bases ----- */
__global__ void findthresh_kernel() {
    int b = blockIdx.x, tid = threadIdx.x;
    __shared__ unsigned int scnt[256];
    __shared__ unsigned int s_running;
    if (tid == 0) s_running = 0;
    __syncthreads();
    int start = (int)g_maxbucket[b];
    for (int cs = start; cs >= 0; cs -= 256) {
        int bk = cs - tid;
        unsigned int c = (bk >= 0) ? g_hist[b][bk] : 0u;
        scnt[tid] = c;
        __syncthreads();
        for (int off = 1; off < 256; off <<= 1) {
            unsigned int v = (tid >= off) ? scnt[tid - off] : 0u;
            __syncthreads();
            scnt[tid] += v;
            __syncthreads();
        }
        unsigned int incl = scnt[tid];
        unsigned int excl = incl - c;
        unsigned int run = s_running;
        if (bk >= 0 && run + excl < KTOP) {
            g_hist[b][bk] = run + excl;
            if (run + incl >= KTOP) {
                g_thresh[b] = bk;
                g_total[b]  = run + incl;
            }
        }
        __syncthreads();
        if (tid == 0) s_running = run + scnt[255];
        __syncthreads();
        if (s_running >= KTOP) break;
    }
}

/* ---------------- kernel 3: compact candidates (grouped by bucket) ------ */
__global__ void compact_kernel(const float* __restrict__ probs) {
    int b = blockIdx.y;
    int tb = g_thresh[b];
    const float* p = probs + (size_t)b * NA * 2;
    for (int a = blockIdx.x * blockDim.x + threadIdx.x; a < NA;
         a += gridDim.x * blockDim.x) {
        unsigned int key = fkey(p[2 * a + 1]);
        unsigned int bk = key >> SHIFT;
        if ((int)bk >= tb) {
            unsigned int pos = atomicAdd(&g_hist[b][bk], 1u);
            if (pos < CAP)
                g_cand[b][pos] =
                    ((unsigned long long)key << 32) | (unsigned int)(~a);
        }
    }
}

/* ---------------- kernel 4: bitonic sort + gather + box decode ---------- */
__global__ void __launch_bounds__(1024, 1)
sort_gather_kernel(const float* __restrict__ bbox,
                   const float* __restrict__ anchors) {
    extern __shared__ unsigned long long s[];
    int b = blockIdx.x, tid = threadIdx.x;
    for (int i = tid; i < SORTN; i += blockDim.x) s[i] = g_cand[b][i];
    __syncthreads();
    for (int k = 2; k <= SORTN; k <<= 1) {
        for (int j = k >> 1; j > 0; j >>= 1) {
            for (int i = tid; i < SORTN; i += blockDim.x) {
                int ixj = i ^ j;
                if (ixj > i) {
                    unsigned long long x = s[i], y = s[ixj];
                    bool up = ((i & k) == 0);
                    if (up ? (x < y) : (x > y)) { s[i] = y; s[ixj] = x; }
                }
            }
            __syncthreads();
        }
    }
    const float4* anc = (const float4*)(anchors + (size_t)b * NA * 4);
    const float4* dl  = (const float4*)(bbox    + (size_t)b * NA * 4);
    for (int i = tid; i < KTOP; i += blockDim.x) {
        unsigned int idx = ~(unsigned int)(s[i]);
        float4 a4 = anc[idx];
        float4 r4 = dl[idx];
        float d0 = __fmul_rn(r4.x, 0.1f);
        float d1 = __fmul_rn(r4.y, 0.1f);
        float d2 = __fmul_rn(r4.z, 0.2f);
        float d3 = __fmul_rn(r4.w, 0.2f);
        float h  = __fsub_rn(a4.z, a4.x);
        float w  = __fsub_rn(a4.w, a4.y);
        float cy = __fadd_rn(__fadd_rn(a4.x, __fmul_rn(0.5f, h)), __fmul_rn(d0, h));
        float cx = __fadd_rn(__fadd_rn(a4.y, __fmul_rn(0.5f, w)), __fmul_rn(d1, w));
        float h2 = __fmul_rn(h, expf(d2));
        float w2 = __fmul_rn(w, expf(d3));
        float y1 = __fsub_rn(cy, __fmul_rn(0.5f, h2));
        float x1 = __fsub_rn(cx, __fmul_rn(0.5f, w2));
        float y2 = __fadd_rn(y1, h2);
        float x2 = __fadd_rn(x1, w2);
        y1 = fminf(fmaxf(y1, 0.0f), 1.0f);
        x1 = fminf(fmaxf(x1, 0.0f), 1.0f);
        y2 = fminf(fmaxf(y2, 0.0f), 1.0f);
        x2 = fminf(fmaxf(x2, 0.0f), 1.0f);
        g_boxes[b * KTOP + i] = make_float4(y1, x1, y2, x2);
        g_areas[b * KTOP + i] = __fmul_rn(__fsub_rn(y2, y1), __fsub_rn(x2, x1));
    }
}

/* ------- kernel 5: suppression-mask build (warp-per-row, lane-per-j) ---- */
#define MBK_THREADS 256
#define MBK_ROWS    32        /* rows per block (8 warps x 4 rows) */
#define MBK_CHUNK   2048

__global__ void __launch_bounds__(MBK_THREADS)
mask_build_kernel() {
    int b       = blockIdx.y;
    int rowbase = blockIdx.x * MBK_ROWS;
    int warp    = threadIdx.x >> 5;
    int lane    = threadIdx.x & 31;

    __shared__ float4 sbox[MBK_CHUNK];
    __shared__ float  sarea[MBK_CHUNK];

    const float4* boxes = g_boxes + b * KTOP;
    const float*  areas = g_areas + b * KTOP;

    for (int chunk = 0; chunk < KTOP; chunk += MBK_CHUNK) {
        int cn = min(MBK_CHUNK, KTOP - chunk);
        __syncthreads();
        for (int t = threadIdx.x; t < cn; t += MBK_THREADS) {
            sbox[t]  = boxes[chunk + t];
            sarea[t] = areas[chunk + t];
        }
        __syncthreads();
        /* nothing in this chunk is >= any of this block's rows? skip */
        if (chunk + cn <= rowbase) continue;
#pragma unroll
        for (int r = 0; r < 4; ++r) {
            int i = rowbase + warp * 4 + r;          /* warp-uniform row */
            if (i >= KTOP) break;
            float4 rb = boxes[i];                    /* broadcast load   */
            float  ra = areas[i];
            int wstart = (i > chunk) ? ((i - chunk) >> 5) : 0;
            int wend   = (cn + 31) >> 5;
            for (int wd = wstart; wd < wend; ++wd) {
                int j = chunk + wd * 32 + lane;
                bool sup = false;
                if (j < KTOP) {
                    float4 cbx = sbox[wd * 32 + lane];
                    float  cax = sarea[wd * 32 + lane];
                    float yy1 = fmaxf(rb.x, cbx.x);
                    float xx1 = fmaxf(rb.y, cbx.y);
                    float yy2 = fminf(rb.z, cbx.z);
                    float xx2 = fminf(rb.w, cbx.w);
                    float inter = __fmul_rn(fmaxf(__fsub_rn(yy2, yy1), 0.0f),
                                            fmaxf(__fsub_rn(xx2, xx1), 0.0f));
                    if (inter > 0.0f) {
                        float uni = __fsub_rn(__fadd_rn(ra, cax), inter);
                        if (uni > 0.0f)
                            sup = !(__fdiv_rn(inter, uni) <= 0.7f);
                    }
                }
                unsigned int word = __ballot_sync(0xFFFFFFFFu, sup);
                if (lane == 0)
                    g_mask[b][i][(chunk >> 5) + wd] = word;
            }
        }
    }
}

/* ------- kernel 6: warp-serial greedy pass, 4-wide speculative ---------- */
__global__ void __launch_bounds__(32, 1)
nms_serial_kernel(float* __restrict__ out) {
    int b    = blockIdx.x;
    int lane = threadIdx.x;
    __shared__ int s_picks[PROP];

    /* valid bitmap: u64 word wu = g*32 + lane covers bits [wu*64, wu*64+63] */
    unsigned long long V[3];
#pragma unroll
    for (int g = 0; g < 3; ++g) {
        int wu = g * 32 + lane;
        V[g] = (wu < 93) ? ~0ull
             : (wu == 93) ? ((1ull << 48) - 1ull) : 0ull;
    }

    const unsigned long long* mask64 =
        (const unsigned long long*)&g_mask[b][0][0];

    int step = 0;
    int done_fill = -1;
    int gstart = 0;                       /* picks are monotone */

    while (step < PROP) {
        /* ---- find up to 4 candidate picks (first 4 set bits of V) ---- */
        unsigned long long T0 = V[0], T1 = V[1], T2 = V[2];
        int cand[4];
        unsigned long long m[4][3];
        int ncand = 0;
#pragma unroll
        for (int s = 0; s < 4; ++s) {
            int pick = -1;
#pragma unroll
            for (int g = 0; g < 3; ++g) {
                if (g >= gstart && pick < 0) {
                    unsigned long long tg = (g == 0) ? T0 : (g == 1) ? T1 : T2;
                    unsigned int ball = __ballot_sync(0xFFFFFFFFu, tg != 0ull);
                    if (ball) {
                        int sel = __ffs(ball) - 1;
                        unsigned long long w = __shfl_sync(0xFFFFFFFFu, tg, sel);
                        pick = g * 2048 + sel * 64 +
                               (__ffsll((long long)w) - 1);
                        if (lane == sel) {     /* clear lowest set bit */
                            if (g == 0)      T0 &= T0 - 1ull;
                            else if (g == 1) T1 &= T1 - 1ull;
                            else             T2 &= T2 - 1ull;
                        }
                    }
                }
            }
            cand[s] = pick;
            if (pick >= 0) {
                const unsigned long long* row = mask64 + (size_t)pick * MASKW64;
                m[s][0] = row[lane];
                m[s][1] = row[lane + 32];
                m[s][2] = row[lane + 64];
                ncand++;
            } else {
                m[s][0] = m[s][1] = m[s][2] = 0ull;
            }
        }
        if (ncand == 0) break;            /* exhausted -> zeros remain */
        gstart = cand[0] >> 11;

        /* ---- validate candidates in order against accepted masks ---- */
        unsigned long long acc0 = 0ull, acc1 = 0ull, acc2 = 0ull;
#pragma unroll
        for (int s = 0; s < 4; ++s) {
            int c = cand[s];
            if (c < 0) break;
            int wdi   = c >> 6;
            int g     = wdi >> 5;
            int owner = wdi & 31;
            int bidx  = c & 63;
            unsigned long long accw = (g == 0) ? acc0 : (g == 1) ? acc1 : acc2;
            unsigned long long wv = __shfl_sync(0xFFFFFFFFu, accw, owner);
            if (!((wv >> bidx) & 1ull)) {      /* not suppressed: accept */
                if (step >= PROP) break;
                if (lane == 0) s_picks[step] = c;
                step++;
                unsigned long long selfreg =
                    (g == 0) ? m[s][0] : (g == 1) ? m[s][1] : m[s][2];
                unsigned long long sw = __shfl_sync(0xFFFFFFFFu, selfreg, owner);
                acc0 |= m[s][0]; acc1 |= m[s][1]; acc2 |= m[s][2];
                if (!((sw >> bidx) & 1ull)) {  /* degenerate: repeats forever */
                    done_fill = c;
                    break;
                }
            }
        }
        V[0] &= ~acc0; V[1] &= ~acc1; V[2] &= ~acc2;
        if (done_fill >= 0) break;
    }

    /* ---- fill remainder + output gather ---- */
    for (int s2 = step + lane; s2 < PROP; s2 += 32) s_picks[s2] = done_fill;
    __syncwarp();
    const float4* boxes = g_boxes + b * KTOP;
    float4* o = (float4*)out + b * PROP;
    for (int s2 = lane; s2 < PROP; s2 += 32) {
        int p = s_picks[s2];
        o[s2] = (p >= 0) ? boxes[p] : make_float4(0.f, 0.f, 0.f, 0.f);
    }
}

/* ---------------- launch ------------------------------------------------ */
extern "C" void kernel_launch(void* const* d_in, const int* in_sizes, int n_in,
                              void* d_out, int out_size) {
    const float* probs   = (const float*)d_in[0];  /* (B, A, 2) */
    const float* bbox    = (const float*)d_in[1];  /* (B, A, 4) */
    const float* anchors = (const float*)d_in[2];  /* (B, A, 4) */
    float* out = (float*)d_out;                    /* (B, 1000, 4) */

    cudaFuncSetAttribute(sort_gather_kernel,
                         cudaFuncAttributeMaxDynamicSharedMemorySize, SORTN * 8);

    clear_kernel<<<1024, 256>>>();
    dim3 hg(256, BATCH);
    hist_kernel<<<hg, 256>>>(probs);
    findthresh_kernel<<<BATCH, 256>>>();
    compact_kernel<<<hg, 256>>>(probs);
    sort_gather_kernel<<<BATCH, 1024, SORTN * 8>>>(bbox, anchors);
    dim3 mg((KTOP + MBK_ROWS - 1) / MBK_ROWS, BATCH);
    mask_build_kernel<<<mg, MBK_THREADS>>>();
    nms_serial_kernel<<<BATCH, 32>>>(out);
}